// round 13
// baseline (speedup 1.0000x reference)
#include <cuda_runtime.h>
#include <cuda_bf16.h>
#include <stdint.h>

// RandomShiftsAug == integer shift + replicate-pad gather:
//   out[n,c,i,j] = x[n,c, clamp(i+sy-4,0,223), clamp(j+sx-4,0,223)]
// (grid coords are exactly integer: iy = i + shift_y, ix = j + shift_x;
//  bilinear weights degenerate to {1,0}).
//
// CONVERGED at the chip memory wall (R4-R12 sweep):
//  - warp-stride-32 column mapping: each warp LDG.32 = 128 contiguous bytes
//    (<=2 lines with dx misalignment), each warp STG.32 = exactly one aligned
//    128B line (row pitch 896B = 7*128B)
//  - plain __ldg/stores (streaming hints measured -3.6% in R7)
//  - 1 row/thread, MLP=7 (MLP=14 measured neutral: DRAM cap-bound)
// Measured 6.1-6.32 TB/s across identical-binary re-runs = B300 LTS chip cap
// (~6300 B/cyc, path-independent) with +-3.5% run-to-run spread; traffic is
// compulsory-minimal (407 MB effective vs 462 MB nominal). All other
// resources idle (issue ~23%, L1 ~43%, compute <15%).

#define H 224
#define W 224
#define C 9
#define PAD 4
#define ROWS 8   // rows per block (blockDim.y)

__global__ __launch_bounds__(256) void random_shift_kernel(
    const float* __restrict__ x,
    const int*   __restrict__ shift,
    float*       __restrict__ out)
{
    const int nc = blockIdx.y;                    // 0 .. n*C-1
    const int n  = nc / C;
    const int i  = blockIdx.x * ROWS + threadIdx.y;   // output row
    const int tx = threadIdx.x;                   // 0..31, column phase

    const int dx = __ldg(shift + 2 * n + 0) - PAD;    // [-4, 4]
    const int dy = __ldg(shift + 2 * n + 1) - PAD;    // [-4, 4]

    const int si = min(max(i + dy, 0), H - 1);
    const float* __restrict__ src = x   + ((size_t)nc * H + si) * W;
    float*       __restrict__ dst = out + ((size_t)nc * H + i) * W;

    // 224 = 7 * 32 columns per row; thread tx owns columns tx + 32*c.
    float v[7];
    #pragma unroll
    for (int c = 0; c < 7; c++) {
        const int j = tx + 32 * c;
        v[c] = __ldg(src + min(max(j + dx, 0), W - 1));
    }
    #pragma unroll
    for (int c = 0; c < 7; c++) {
        dst[tx + 32 * c] = v[c];
    }
}

extern "C" void kernel_launch(void* const* d_in, const int* in_sizes, int n_in,
                              void* d_out, int out_size)
{
    const float* x     = (const float*)d_in[0];   // (128, 9, 224, 224) fp32
    const int*   shift = (const int*)d_in[1];     // (128, 1, 1, 2) int32
    float* out = (float*)d_out;

    const int n = in_sizes[1] / 2;                // 128 batches

    dim3 block(32, ROWS, 1);                      // 256 threads
    dim3 grid(H / ROWS, n * C, 1);                // (28, 1152)
    random_shift_kernel<<<grid, block>>>(x, shift, out);
}

// round 15
// speedup vs baseline: 1.0054x; 1.0054x over previous
#include <cuda_runtime.h>
#include <cuda_bf16.h>
#include <stdint.h>

// RandomShiftsAug == integer shift + replicate-pad gather:
//   out[n,c,i,j] = x[n,c, clamp(i+sy-4,0,223), clamp(j+sx-4,0,223)]
// (grid coords are exactly integer: iy = i + shift_y, ix = j + shift_x;
//  bilinear weights degenerate to {1,0}).
//
// CONVERGED at the chip memory wall (R4-R13 sweep, 3x identical-binary runs):
//  - warp-stride-32 column mapping: each warp LDG.32 = 128 contiguous bytes
//    (<=2 lines with dx misalignment), each warp STG.32 = exactly one aligned
//    128B line (row pitch 896B = 7*128B)
//  - plain __ldg/stores (streaming hints measured -3.6%)
//  - 1 row/thread, MLP=7 (MLP=14 measured neutral: DRAM cap-bound)
// Measured 6.09-6.32 TB/s across identical-binary re-runs = B300 LTS chip cap
// (~6300 B/cyc, path-independent) with ~+-2% run-to-run spread; traffic is
// compulsory-minimal (407 MB effective vs 462 MB nominal). All other
// resources idle (issue ~23%, L1 ~43%, compute <15%). ncu best 64.4us.

#define H 224
#define W 224
#define C 9
#define PAD 4
#define ROWS 8   // rows per block (blockDim.y)

__global__ __launch_bounds__(256) void random_shift_kernel(
    const float* __restrict__ x,
    const int*   __restrict__ shift,
    float*       __restrict__ out)
{
    const int nc = blockIdx.y;                    // 0 .. n*C-1
    const int n  = nc / C;
    const int i  = blockIdx.x * ROWS + threadIdx.y;   // output row
    const int tx = threadIdx.x;                   // 0..31, column phase

    const int dx = __ldg(shift + 2 * n + 0) - PAD;    // [-4, 4]
    const int dy = __ldg(shift + 2 * n + 1) - PAD;    // [-4, 4]

    const int si = min(max(i + dy, 0), H - 1);
    const float* __restrict__ src = x   + ((size_t)nc * H + si) * W;
    float*       __restrict__ dst = out + ((size_t)nc * H + i) * W;

    // 224 = 7 * 32 columns per row; thread tx owns columns tx + 32*c.
    float v[7];
    #pragma unroll
    for (int c = 0; c < 7; c++) {
        const int j = tx + 32 * c;
        v[c] = __ldg(src + min(max(j + dx, 0), W - 1));
    }
    #pragma unroll
    for (int c = 0; c < 7; c++) {
        dst[tx + 32 * c] = v[c];
    }
}

extern "C" void kernel_launch(void* const* d_in, const int* in_sizes, int n_in,
                              void* d_out, int out_size)
{
    const float* x     = (const float*)d_in[0];   // (128, 9, 224, 224) fp32
    const int*   shift = (const int*)d_in[1];     // (128, 1, 1, 2) int32
    float* out = (float*)d_out;

    const int n = in_sizes[1] / 2;                // 128 batches

    dim3 block(32, ROWS, 1);                      // 256 threads
    dim3 grid(H / ROWS, n * C, 1);                // (28, 1152)
    random_shift_kernel<<<grid, block>>>(x, shift, out);
}

// round 17
// speedup vs baseline: 1.0205x; 1.0151x over previous
#include <cuda_runtime.h>
#include <cuda_bf16.h>
#include <stdint.h>

// RandomShiftsAug == integer shift + replicate-pad gather:
//   out[n,c,i,j] = x[n,c, clamp(i+sy-4,0,223), clamp(j+sx-4,0,223)]
// (grid coords are exactly integer: iy = i + shift_y, ix = j + shift_x;
//  bilinear weights degenerate to {1,0}).
//
// CONVERGED at the chip memory wall (R4-R15 sweep, 4x identical-binary runs:
// ncu {64.4, 67.1, 65.2, 65.0} us, HBM {6318, 6093, 6248, 6265} GB/s):
//  - warp-stride-32 column mapping: each warp LDG.32 = 128 contiguous bytes
//    (<=2 lines with dx misalignment), each warp STG.32 = exactly one aligned
//    128B line (row pitch 896B = 7*128B)
//  - plain __ldg/stores (streaming hints measured -3.6%)
//  - 1 row/thread, MLP=7 (MLP=14 measured neutral: DRAM cap-bound)
// 6.25 TB/s mean = B300 LTS chip cap (~6300 B/cyc, path-independent);
// traffic compulsory-minimal (407 MB effective vs 462 MB nominal). All other
// resources idle (issue ~23%, L1 ~43%, compute <15%).

#define H 224
#define W 224
#define C 9
#define PAD 4
#define ROWS 8   // rows per block (blockDim.y)

__global__ __launch_bounds__(256) void random_shift_kernel(
    const float* __restrict__ x,
    const int*   __restrict__ shift,
    float*       __restrict__ out)
{
    const int nc = blockIdx.y;                    // 0 .. n*C-1
    const int n  = nc / C;
    const int i  = blockIdx.x * ROWS + threadIdx.y;   // output row
    const int tx = threadIdx.x;                   // 0..31, column phase

    const int dx = __ldg(shift + 2 * n + 0) - PAD;    // [-4, 4]
    const int dy = __ldg(shift + 2 * n + 1) - PAD;    // [-4, 4]

    const int si = min(max(i + dy, 0), H - 1);
    const float* __restrict__ src = x   + ((size_t)nc * H + si) * W;
    float*       __restrict__ dst = out + ((size_t)nc * H + i) * W;

    // 224 = 7 * 32 columns per row; thread tx owns columns tx + 32*c.
    float v[7];
    #pragma unroll
    for (int c = 0; c < 7; c++) {
        const int j = tx + 32 * c;
        v[c] = __ldg(src + min(max(j + dx, 0), W - 1));
    }
    #pragma unroll
    for (int c = 0; c < 7; c++) {
        dst[tx + 32 * c] = v[c];
    }
}

extern "C" void kernel_launch(void* const* d_in, const int* in_sizes, int n_in,
                              void* d_out, int out_size)
{
    const float* x     = (const float*)d_in[0];   // (128, 9, 224, 224) fp32
    const int*   shift = (const int*)d_in[1];     // (128, 1, 1, 2) int32
    float* out = (float*)d_out;

    const int n = in_sizes[1] / 2;                // 128 batches

    dim3 block(32, ROWS, 1);                      // 256 threads
    dim3 grid(H / ROWS, n * C, 1);                // (28, 1152)
    random_shift_kernel<<<grid, block>>>(x, shift, out);
}